// round 2
// baseline (speedup 1.0000x reference)
#include <cuda_runtime.h>
#include <cstdint>

#define B_SZ 4
#define D_SZ 32
#define N_SZ 4096
#define BM 64
#define TN 64
#define NTILES (N_SZ / TN)
#define THREADS 256

// ping/pong scratch for the iteration chain (no cudaMalloc allowed)
__device__ float g_ping[B_SZ * D_SZ * N_SZ];
__device__ float g_pong[B_SZ * D_SZ * N_SZ];

// ---- packed fp32x2 helpers (Blackwell dual fp32) ----
// NOTE: fma.rn.f32x2 needs .b64 regs -> use "l" (u64) constraints, NOT "d" (.f64).
__device__ __forceinline__ uint64_t ffma2(uint64_t a, uint64_t b, uint64_t c) {
    uint64_t r;
    asm("fma.rn.f32x2 %0, %1, %2, %3;" : "=l"(r) : "l"(a), "l"(b), "l"(c));
    return r;
}
__device__ __forceinline__ uint64_t pack2(float lo, float hi) {
    uint64_t r;
    asm("mov.b64 %0, {%1, %2};" : "=l"(r) : "f"(lo), "f"(hi));
    return r;
}
__device__ __forceinline__ void unpack2(uint64_t v, float &lo, float &hi) {
    asm("mov.b64 {%0, %1}, %2;" : "=f"(lo), "=f"(hi) : "l"(v));
}

// One mean-shift iteration:
//   K[n,m] = exp(0.1 * <Y[:,n], Y[:,m]>)
//   S[m]   = sum_n K[n,m]
//   Yout[:,m] = 0.5 * (Y K)[:,m] / S[m] + 0.5 * Y[:,m]
// Each CTA owns BM=64 output columns of one batch and streams all N in TN=64 tiles.
__global__ __launch_bounds__(THREADS) void ms_iter(const float* __restrict__ xin,
                                                   float* __restrict__ xout,
                                                   int mode) {
    __shared__ float Yn_s[D_SZ][TN + 4];   // +4 pad: kills 32-way conflicts on column reads
    __shared__ float Ym_s[D_SZ][BM];
    __shared__ float K_s[TN][BM];
    __shared__ float Sp_s[4][BM];

    const float* gin  = (mode == 0) ? xin    : (mode == 1 ? g_ping : g_pong);
    float*       gout = (mode == 0) ? g_ping : (mode == 1 ? g_pong : xout);

    const int t  = threadIdx.x;
    const int b  = blockIdx.y;
    const int m0 = blockIdx.x * BM;
    const float* Y = gin  + b * (D_SZ * N_SZ);
    float*       O = gout + b * (D_SZ * N_SZ);

    // ---- load Ym tile (loop-invariant): 2x float4 per thread ----
    #pragma unroll
    for (int r = 0; r < 2; r++) {
        int v = t + r * THREADS;          // 0..511 float4s
        int d = v >> 4, nv = v & 15;
        *(float4*)&Ym_s[d][nv * 4] = *(const float4*)&Y[d * N_SZ + m0 + nv * 4];
    }

    // phase A ids: 16x16 threads, 4x4 micro-tile of K
    const int tx = t & 15, ty = t >> 4;
    // phase B ids: 4 n-subsets x (8 d-groups x 8 m-groups)
    const int nsub = t >> 6;              // 0..3
    const int rr   = t & 63;
    const int d0   = (rr >> 3) * 4;       // 0,4,...,28
    const int mB   = (rr & 7) * 8;        // 0,8,...,56
    // S-pass ids: thread sums a 16-row strip of one column
    const int sm  = t & 63;
    const int sn0 = (t >> 6) * 16;

    uint64_t Z2[4][4];                    // Z partials: 4 d x 8 m (packed pairs)
    #pragma unroll
    for (int i = 0; i < 4; i++)
        #pragma unroll
        for (int j = 0; j < 4; j++) Z2[i][j] = 0ull;
    float S_reg = 0.0f;

    for (int nt = 0; nt < NTILES; nt++) {
        const int n0 = nt * TN;
        __syncthreads();                  // Yn_s / K_s safe to overwrite
        // ---- load Yn tile ----
        #pragma unroll
        for (int r = 0; r < 2; r++) {
            int v = t + r * THREADS;
            int d = v >> 4, nv = v & 15;
            *(float4*)&Yn_s[d][nv * 4] = *(const float4*)&Y[d * N_SZ + n0 + nv * 4];
        }
        __syncthreads();                  // Yn ready (also orders Ym on nt==0)

        // ---- phase A: K_s = exp(0.1 * Yn^T * Ym), 4x4 per thread ----
        uint64_t acc2[4][2];
        #pragma unroll
        for (int i = 0; i < 4; i++) { acc2[i][0] = 0ull; acc2[i][1] = 0ull; }
        #pragma unroll
        for (int d = 0; d < D_SZ; d++) {
            float4     a  = *(const float4*)&Yn_s[d][ty * 4];
            ulonglong2 bv = *(const ulonglong2*)&Ym_s[d][tx * 4];
            uint64_t a0 = pack2(a.x, a.x);
            uint64_t a1 = pack2(a.y, a.y);
            uint64_t a2 = pack2(a.z, a.z);
            uint64_t a3 = pack2(a.w, a.w);
            acc2[0][0] = ffma2(a0, bv.x, acc2[0][0]);
            acc2[0][1] = ffma2(a0, bv.y, acc2[0][1]);
            acc2[1][0] = ffma2(a1, bv.x, acc2[1][0]);
            acc2[1][1] = ffma2(a1, bv.y, acc2[1][1]);
            acc2[2][0] = ffma2(a2, bv.x, acc2[2][0]);
            acc2[2][1] = ffma2(a2, bv.y, acc2[2][1]);
            acc2[3][0] = ffma2(a3, bv.x, acc2[3][0]);
            acc2[3][1] = ffma2(a3, bv.y, acc2[3][1]);
        }
        #pragma unroll
        for (int i = 0; i < 4; i++) {
            float f0, f1, f2, f3;
            unpack2(acc2[i][0], f0, f1);
            unpack2(acc2[i][1], f2, f3);
            float4 kv;
            kv.x = __expf(0.1f * f0);
            kv.y = __expf(0.1f * f1);
            kv.z = __expf(0.1f * f2);
            kv.w = __expf(0.1f * f3);
            *(float4*)&K_s[ty * 4 + i][tx * 4] = kv;
        }
        __syncthreads();                  // K ready

        // ---- S partial: each thread sums 16 rows of its column ----
        #pragma unroll
        for (int k = 0; k < 16; k++) S_reg += K_s[sn0 + k][sm];

        // ---- phase B: Z[d0..d0+3][mB..mB+7] += Yn * K over this tile's n-subset ----
        #pragma unroll
        for (int q = 0; q < 16; q++) {
            const int n = nsub + q * 4;
            ulonglong2 k0 = *(const ulonglong2*)&K_s[n][mB];
            ulonglong2 k1 = *(const ulonglong2*)&K_s[n][mB + 4];
            float yv0 = Yn_s[d0 + 0][n];
            float yv1 = Yn_s[d0 + 1][n];
            float yv2 = Yn_s[d0 + 2][n];
            float yv3 = Yn_s[d0 + 3][n];
            uint64_t y0 = pack2(yv0, yv0);
            uint64_t y1 = pack2(yv1, yv1);
            uint64_t y2 = pack2(yv2, yv2);
            uint64_t y3 = pack2(yv3, yv3);
            Z2[0][0] = ffma2(y0, k0.x, Z2[0][0]);
            Z2[0][1] = ffma2(y0, k0.y, Z2[0][1]);
            Z2[0][2] = ffma2(y0, k1.x, Z2[0][2]);
            Z2[0][3] = ffma2(y0, k1.y, Z2[0][3]);
            Z2[1][0] = ffma2(y1, k0.x, Z2[1][0]);
            Z2[1][1] = ffma2(y1, k0.y, Z2[1][1]);
            Z2[1][2] = ffma2(y1, k1.x, Z2[1][2]);
            Z2[1][3] = ffma2(y1, k1.y, Z2[1][3]);
            Z2[2][0] = ffma2(y2, k0.x, Z2[2][0]);
            Z2[2][1] = ffma2(y2, k0.y, Z2[2][1]);
            Z2[2][2] = ffma2(y2, k1.x, Z2[2][2]);
            Z2[2][3] = ffma2(y2, k1.y, Z2[2][3]);
            Z2[3][0] = ffma2(y3, k0.x, Z2[3][0]);
            Z2[3][1] = ffma2(y3, k0.y, Z2[3][1]);
            Z2[3][2] = ffma2(y3, k1.x, Z2[3][2]);
            Z2[3][3] = ffma2(y3, k1.y, Z2[3][3]);
        }
    }

    // ---- epilogue: reduce the 4 n-subset partials, normalize, blend, store ----
    Sp_s[t >> 6][t & 63] = S_reg;
    __syncthreads();                      // phase B done; K_s reusable; Sp visible

    float* Zr = &K_s[0][0];               // 32x64 accumulator, reuse K_s
    #pragma unroll
    for (int s = 0; s < 4; s++) {
        if (nsub == s) {
            #pragma unroll
            for (int i = 0; i < 4; i++)
                #pragma unroll
                for (int jp = 0; jp < 4; jp++) {
                    float lo, hi;
                    unpack2(Z2[i][jp], lo, hi);
                    int base = (d0 + i) * BM + mB + jp * 2;
                    if (s == 0) { Zr[base] = lo;  Zr[base + 1] = hi; }
                    else        { Zr[base] += lo; Zr[base + 1] += hi; }
                }
        }
        __syncthreads();
    }

    for (int r2 = t; r2 < D_SZ * BM; r2 += THREADS) {
        int d = r2 >> 6, m = r2 & 63;
        float Ssum = Sp_s[0][m] + Sp_s[1][m] + Sp_s[2][m] + Sp_s[3][m];
        float val = 0.5f * Zr[r2] / Ssum + 0.5f * Ym_s[d][m];
        O[d * N_SZ + m0 + m] = val;
    }
}

extern "C" void kernel_launch(void* const* d_in, const int* in_sizes, int n_in,
                              void* d_out, int out_size) {
    const float* x = (const float*)d_in[0];
    float* out = (float*)d_out;
    dim3 grid(N_SZ / BM, B_SZ);
    ms_iter<<<grid, THREADS>>>(x, out, 0);   // x      -> g_ping
    ms_iter<<<grid, THREADS>>>(x, out, 1);   // g_ping -> g_pong
    ms_iter<<<grid, THREADS>>>(x, out, 2);   // g_pong -> out
}

// round 4
// speedup vs baseline: 3.8458x; 3.8458x over previous
#include <cuda_runtime.h>
#include <cstdint>

#define B_SZ 4
#define D_SZ 32
#define N_SZ 4096
#define BM 128
#define TN 128
#define NTILES (N_SZ / TN)
#define THREADS 256
#define YS 132                 // stride (floats) of natural [d][*] tiles
#define KS 132                 // stride (floats) of Kt tile

// ping/pong scratch for the iteration chain (no cudaMalloc allowed)
__device__ float g_ping[B_SZ * D_SZ * N_SZ];
__device__ float g_pong[B_SZ * D_SZ * N_SZ];

// smem float offsets
#define OFF_YM 0
#define OFF_YN (D_SZ * YS)                  // 4224
#define OFF_KT (2 * D_SZ * YS)              // 8448
#define OFF_SS (OFF_KT + BM * KS)           // 25344
#define SMEM_FLOATS (OFF_SS + 4 * BM)       // 25856
#define SMEM_BYTES (SMEM_FLOATS * 4)        // 103424

static __device__ __forceinline__ uint32_t to_tf32(float f) {
    uint32_t r; asm("cvt.rna.tf32.f32 %0, %1;" : "=r"(r) : "f"(f)); return r;
}
static __device__ __forceinline__ void mma8(float* c, const uint32_t* a,
                                            uint32_t b0, uint32_t b1) {
    asm("mma.sync.aligned.m16n8k8.row.col.f32.tf32.tf32.f32 "
        "{%0,%1,%2,%3},{%4,%5,%6,%7},{%8,%9},{%0,%1,%2,%3};"
        : "+f"(c[0]), "+f"(c[1]), "+f"(c[2]), "+f"(c[3])
        : "r"(a[0]), "r"(a[1]), "r"(a[2]), "r"(a[3]), "r"(b0), "r"(b1));
}

// One mean-shift iteration, tensor-core path.
//   Kt[m][n] = exp(0.1*<y_m,y_n>);  S[m] = sum_n Kt[m][n] (symmetry)
//   Z[m][d]  = sum_n Kt[m][n]*Y[d][n];  out = 0.5*Z/S + 0.5*Y
__global__ __launch_bounds__(THREADS) void ms_iter_mma(const float* __restrict__ xin,
                                                       float* __restrict__ xout,
                                                       int mode) {
    extern __shared__ float sm[];
    float* ym  = sm + OFF_YM;    // [32][132] tf32 bits, natural [d][m_local]
    float* yn  = sm + OFF_YN;    // [32][132] tf32 bits, natural [d][n_local]
    float* kt  = sm + OFF_KT;    // [128][132] tf32 Kt, swizzled col ^ ((m&3)<<3)
    float* sst = sm + OFF_SS;    // [4][128] S partials per k-slice warp group
    float* zst = kt;             // Z staging aliases kt (after last kt use)

    const float* gin  = (mode == 0) ? xin    : (mode == 1 ? g_ping : g_pong);
    float*       gout = (mode == 0) ? g_ping : (mode == 1 ? g_pong : xout);
    const int b  = blockIdx.y;
    const int m0 = blockIdx.x * BM;
    const float* Y = gin  + b * (D_SZ * N_SZ);
    float*       O = gout + b * (D_SZ * N_SZ);

    const int t    = threadIdx.x;
    const int wid  = t >> 5;
    const int lane = t & 31;
    const int g    = lane >> 2;        // groupID (row within fragment)
    const int k4   = lane & 3;         // threadID_in_group
    const int wm   = wid & 1;          // m-half (64 rows)
    const int wn   = wid >> 1;         // n-slice (32 cols) / k-slice for MMA2
    const int sw   = (g & 3) << 3;     // Kt column swizzle for this thread's rows

    // ---- stage Ym (tf32) into natural [d][m_local] ----
    #pragma unroll
    for (int r = 0; r < 4; r++) {
        int v = t + r * THREADS;             // 0..1023 float4s
        int d = v >> 5, j = (v & 31) * 4;
        float4 x = *(const float4*)&Y[d * N_SZ + m0 + j];
        uint4 u;
        u.x = to_tf32(x.x); u.y = to_tf32(x.y);
        u.z = to_tf32(x.z); u.w = to_tf32(x.w);
        *(uint4*)&ym[d * YS + j] = u;
    }
    __syncthreads();

    // ---- hoist A1 fragments: Ym rows for this warp's m-half, all 4 k-chunks ----
    uint32_t a1[4][4][4];                    // [mi][kc][frag]
    #pragma unroll
    for (int mi = 0; mi < 4; mi++)
        #pragma unroll
        for (int kc = 0; kc < 4; kc++) {
            int mr = wm * 64 + mi * 16 + g;
            int d  = kc * 8 + k4;
            a1[mi][kc][0] = __float_as_uint(ym[d * YS + mr]);
            a1[mi][kc][1] = __float_as_uint(ym[d * YS + mr + 8]);
            a1[mi][kc][2] = __float_as_uint(ym[(d + 4) * YS + mr]);
            a1[mi][kc][3] = __float_as_uint(ym[(d + 4) * YS + mr + 8]);
        }

    float z[4][4][4];                        // persistent Z partials [mi][di][frag]
    #pragma unroll
    for (int i = 0; i < 4; i++)
        #pragma unroll
        for (int j = 0; j < 4; j++)
            #pragma unroll
            for (int q = 0; q < 4; q++) z[i][j][q] = 0.0f;
    float Sp[8];                             // S partials: [mi][rowsel]
    #pragma unroll
    for (int i = 0; i < 8; i++) Sp[i] = 0.0f;

    for (int nt = 0; nt < NTILES; nt++) {
        const int n0 = nt * TN;
        __syncthreads();                     // prev-tile consumers of yn/kt done
        // ---- stage Yn (tf32), natural [d][n_local] ----
        #pragma unroll
        for (int r = 0; r < 4; r++) {
            int v = t + r * THREADS;
            int d = v >> 5, j = (v & 31) * 4;
            float4 x = *(const float4*)&Y[d * N_SZ + n0 + j];
            uint4 u;
            u.x = to_tf32(x.x); u.y = to_tf32(x.y);
            u.z = to_tf32(x.z); u.w = to_tf32(x.w);
            *(uint4*)&yn[d * YS + j] = u;
        }
        __syncthreads();

        // ---- MMA1 (+exp epilogue) in two 16-col halves to cap registers ----
        #pragma unroll
        for (int nh = 0; nh < 2; nh++) {
            float c[2][4][4];
            #pragma unroll
            for (int i = 0; i < 2; i++)
                #pragma unroll
                for (int j = 0; j < 4; j++)
                    #pragma unroll
                    for (int q = 0; q < 4; q++) c[i][j][q] = 0.0f;
            #pragma unroll
            for (int kc = 0; kc < 4; kc++) {
                uint32_t bf[2][2];
                #pragma unroll
                for (int ni = 0; ni < 2; ni++) {
                    int nl = wn * 32 + (nh * 2 + ni) * 8 + g;
                    int d  = kc * 8 + k4;
                    bf[ni][0] = __float_as_uint(yn[d * YS + nl]);
                    bf[ni][1] = __float_as_uint(yn[(d + 4) * YS + nl]);
                }
                #pragma unroll
                for (int mi = 0; mi < 4; mi++)
                    #pragma unroll
                    for (int ni = 0; ni < 2; ni++)
                        mma8(c[ni][mi], a1[mi][kc], bf[ni][0], bf[ni][1]);
            }
            // exp + S + store tf32 Kt (swizzled)
            #pragma unroll
            for (int ni = 0; ni < 2; ni++)
                #pragma unroll
                for (int mi = 0; mi < 4; mi++) {
                    float e0 = __expf(0.1f * c[ni][mi][0]);
                    float e1 = __expf(0.1f * c[ni][mi][1]);
                    float e2 = __expf(0.1f * c[ni][mi][2]);
                    float e3 = __expf(0.1f * c[ni][mi][3]);
                    Sp[mi * 2]     += e0 + e1;
                    Sp[mi * 2 + 1] += e2 + e3;
                    int row = wm * 64 + mi * 16 + g;
                    int col = wn * 32 + (nh * 2 + ni) * 8 + 2 * k4;
                    float2 p0, p1;
                    p0.x = __uint_as_float(to_tf32(e0));
                    p0.y = __uint_as_float(to_tf32(e1));
                    p1.x = __uint_as_float(to_tf32(e2));
                    p1.y = __uint_as_float(to_tf32(e3));
                    *(float2*)&kt[row * KS + (col ^ sw)]       = p0;
                    *(float2*)&kt[(row + 8) * KS + (col ^ sw)] = p1;
                }
        }
        __syncthreads();                     // Kt visible to all warps

        // ---- MMA2: warp's k-slice = n in [wn*32, wn*32+32) of this tile ----
        #pragma unroll
        for (int kc = 0; kc < 4; kc++) {
            const int kcol = wn * 32 + kc * 8 + k4;
            uint32_t a2[4][4];
            #pragma unroll
            for (int mi = 0; mi < 4; mi++) {
                int m = wm * 64 + mi * 16 + g;
                a2[mi][0] = __float_as_uint(kt[m * KS + (kcol ^ sw)]);
                a2[mi][1] = __float_as_uint(kt[(m + 8) * KS + (kcol ^ sw)]);
                a2[mi][2] = __float_as_uint(kt[m * KS + ((kcol + 4) ^ sw)]);
                a2[mi][3] = __float_as_uint(kt[(m + 8) * KS + ((kcol + 4) ^ sw)]);
            }
            uint32_t b2[4][2];
            #pragma unroll
            for (int di = 0; di < 4; di++) {
                int d  = di * 8 + g;
                int nl = wn * 32 + kc * 8 + k4;
                b2[di][0] = __float_as_uint(yn[d * YS + nl]);
                b2[di][1] = __float_as_uint(yn[d * YS + nl + 4]);
            }
            #pragma unroll
            for (int mi = 0; mi < 4; mi++)
                #pragma unroll
                for (int di = 0; di < 4; di++)
                    mma8(z[mi][di], a2[mi], b2[di][0], b2[di][1]);
        }
    }

    // ---- S reduce across the quad (k4 lanes) and publish per k-slice ----
    #pragma unroll
    for (int i = 0; i < 8; i++) {
        Sp[i] += __shfl_xor_sync(0xFFFFFFFFu, Sp[i], 1);
        Sp[i] += __shfl_xor_sync(0xFFFFFFFFu, Sp[i], 2);
    }
    if (k4 == 0) {
        #pragma unroll
        for (int mi = 0; mi < 4; mi++) {
            int row = wm * 64 + mi * 16 + g;
            sst[wn * 128 + row]     = Sp[mi * 2];
            sst[wn * 128 + row + 8] = Sp[mi * 2 + 1];
        }
    }
    __syncthreads();                         // all MMA2 kt reads done -> reuse as zst

    // ---- stage Z partials [wn][m][d] ----
    #pragma unroll
    for (int mi = 0; mi < 4; mi++)
        #pragma unroll
        for (int di = 0; di < 4; di++) {
            int row = wm * 64 + mi * 16 + g;
            int d   = di * 8 + 2 * k4;
            float* p = &zst[wn * 4096 + row * 32 + d];
            p[0] = z[mi][di][0];
            p[1] = z[mi][di][1];
            zst[wn * 4096 + (row + 8) * 32 + d]     = z[mi][di][2];
            zst[wn * 4096 + (row + 8) * 32 + d + 1] = z[mi][di][3];
        }
    __syncthreads();

    // ---- final: sum 4 k-slices, normalize, blend, store ----
    {
        const int m  = t & 127;
        const int d0 = (t >> 7) * 16;
        float Ssum = sst[m] + sst[128 + m] + sst[256 + m] + sst[384 + m];
        float inv = 0.5f / Ssum;
        #pragma unroll
        for (int dd = 0; dd < 16; dd++) {
            int d = d0 + dd;
            float zsum = zst[m * 32 + d] + zst[4096 + m * 32 + d] +
                         zst[8192 + m * 32 + d] + zst[12288 + m * 32 + d];
            O[d * N_SZ + m0 + m] = zsum * inv + 0.5f * Y[d * N_SZ + m0 + m];
        }
    }
}

extern "C" void kernel_launch(void* const* d_in, const int* in_sizes, int n_in,
                              void* d_out, int out_size) {
    const float* x = (const float*)d_in[0];
    float* out = (float*)d_out;
    cudaFuncSetAttribute(ms_iter_mma, cudaFuncAttributeMaxDynamicSharedMemorySize,
                         SMEM_BYTES);
    dim3 grid(N_SZ / BM, B_SZ);
    ms_iter_mma<<<grid, THREADS, SMEM_BYTES>>>(x, out, 0);   // x      -> g_ping
    ms_iter_mma<<<grid, THREADS, SMEM_BYTES>>>(x, out, 1);   // g_ping -> g_pong
    ms_iter_mma<<<grid, THREADS, SMEM_BYTES>>>(x, out, 2);   // g_pong -> out
}